// round 10
// baseline (speedup 1.0000x reference)
#include <cuda_runtime.h>
#include <cstdint>

constexpr int N = 4096;
constexpr int K = 256;
constexpr float MARGIN = 0.3f;
constexpr float BIG = 10000.0f;
constexpr float QSCALE = 4096.0f;
constexpr float INV_DOT = 1.0f / 65536.0f;   // acc*256 / 2^24

// ---------------- scratch (device globals; no runtime alloc) ----------------
__device__ __align__(16) float   g_sq[N];
__device__ __align__(16) unsigned g_max_eq[N];
__device__ __align__(16) unsigned g_min_gt[N];
__device__ __align__(16) unsigned g_min_lt[N];
__device__ __align__(16) int8_t  g_hi[(size_t)N * K];
__device__ __align__(16) int8_t  g_lo[(size_t)N * K];

// ---------------- PTX helpers (base ISA only) ----------------
__device__ __forceinline__ uint32_t smem_u32(const void* p) {
    uint32_t a;
    asm("{ .reg .u64 t; cvta.to.shared.u64 t, %1; cvt.u32.u64 %0, t; }" : "=r"(a) : "l"(p));
    return a;
}
__device__ __forceinline__ void cp16(uint32_t saddr, const void* g) {
    asm volatile("cp.async.cg.shared.global [%0], [%1], 16;" :: "r"(saddr), "l"(g));
}
#define CP_COMMIT() asm volatile("cp.async.commit_group;" ::: "memory")
#define CP_WAIT(n)  asm volatile("cp.async.wait_group %0;" :: "n"(n) : "memory")

__device__ __forceinline__ void ldsm4(uint32_t& r0, uint32_t& r1, uint32_t& r2, uint32_t& r3,
                                      uint32_t addr) {
    asm volatile("ldmatrix.sync.aligned.m8n8.x4.shared.b16 {%0,%1,%2,%3}, [%4];"
                 : "=r"(r0), "=r"(r1), "=r"(r2), "=r"(r3) : "r"(addr));
}
__device__ __forceinline__ void mma_s8(int* d, const uint32_t* a, const uint32_t* b) {
    asm volatile("mma.sync.aligned.m16n8k32.row.col.s32.s8.s8.s32 "
                 "{%0,%1,%2,%3},{%4,%5,%6,%7},{%8,%9},{%0,%1,%2,%3};"
                 : "+r"(d[0]), "+r"(d[1]), "+r"(d[2]), "+r"(d[3])
                 : "r"(a[0]), "r"(a[1]), "r"(a[2]), "r"(a[3]), "r"(b[0]), "r"(b[1]));
}

// ---------------- kernels ----------------
__global__ void k_prep(const float* __restrict__ X, const int* __restrict__ T) {
    int warp = threadIdx.x >> 5, lane = threadIdx.x & 31;
    int row = blockIdx.x * 8 + warp;
    const float4* p = reinterpret_cast<const float4*>(X + (size_t)row * K);
    float4 a = p[lane * 2];
    float4 b = p[lane * 2 + 1];
    float xs[8] = {a.x, a.y, a.z, a.w, b.x, b.y, b.z, b.w};
    float s = 0.0f;
    int8_t hb[8], lb[8];
    #pragma unroll
    for (int e = 0; e < 8; ++e) {
        s = fmaf(xs[e], xs[e], s);
        int q  = __float2int_rn(xs[e] * QSCALE);
        int hi = (q + 128) >> 8;              // round-to-nearest split
        int lo = q - (hi << 8);               // in [-128, 127]
        hb[e] = (int8_t)hi;
        lb[e] = (int8_t)lo;
    }
    size_t off = (size_t)row * K + lane * 8;
    *reinterpret_cast<uint2*>(&g_hi[off]) = *reinterpret_cast<uint2*>(hb);
    *reinterpret_cast<uint2*>(&g_lo[off]) = *reinterpret_cast<uint2*>(lb);
    #pragma unroll
    for (int o = 16; o >= 1; o >>= 1) s += __shfl_xor_sync(0xffffffffu, s, o);
    if (lane == 0) {
        g_sq[row]     = s;
        g_max_eq[row] = 0u;
        g_min_gt[row] = __float_as_uint(BIG);
        g_min_lt[row] = __float_as_uint(BIG);
    }
}

// SMEM layout (dynamic):
//   [0] sqj[128]  [512] tj[128]  [1024] sqi[128]  [1536] ti[128]
//   mainloop:  [2048] A0(16K) [18432] B0 [34816] A1 [51200] B1   (end 67584)
//   epilogue:  [2048] staging tile 128 x 129 floats (66048 B, end 68096)
constexpr int SM_SQJ = 0, SM_TJ = 512, SM_SQI = 1024, SM_TI = 1536;
constexpr int SM_A0 = 2048, SM_B0 = 18432, SM_A1 = 34816, SM_B1 = 51200;
constexpr int SM_TILE = 2048;
constexpr int SMEM_TOTAL = 68096;
constexpr int NUM_KB = 6;    // 3 s8 passes (hh, hl, lh) x (256 elem / 128 per kb)
constexpr int NBLK = 32;
constexpr int NTRI = NBLK * (NBLK + 1) / 2;  // 528

__global__ void __launch_bounds__(256, 2)
k_dist_mma(const int* __restrict__ T, float* __restrict__ dist) {
    extern __shared__ char smem[];
    const uint32_t smem_base = smem_u32(smem);
    const int tid  = threadIdx.x;
    const int lane = tid & 31, wid = tid >> 5;
    const int wm = wid & 3, wn = wid >> 2;        // warp tile: 32 rows x 64 cols

    // triangular decode: by >= bx
    int idx = blockIdx.x;
    int by = (int)((sqrtf(8.0f * (float)idx + 1.0f) - 1.0f) * 0.5f);
    while ((by + 1) * (by + 2) / 2 <= idx) ++by;
    while (by * (by + 1) / 2 > idx) --by;
    const int bx = idx - by * (by + 1) / 2;
    const int bm = by * 128;
    const int bn = bx * 128;
    const bool diag = (by == bx);

    float* sqj = reinterpret_cast<float*>(smem + SM_SQJ);
    int*   tjs = reinterpret_cast<int*>(smem + SM_TJ);
    float* sqi = reinterpret_cast<float*>(smem + SM_SQI);
    int*   tis = reinterpret_cast<int*>(smem + SM_TI);
    if (tid < 128) { sqj[tid] = g_sq[bn + tid]; tjs[tid] = T[bn + tid]; }
    else { int t2 = tid - 128; sqi[t2] = g_sq[bm + t2]; tis[t2] = T[bm + t2]; }

    const int aoff[2] = {SM_A0, SM_A1};
    const int boff[2] = {SM_B0, SM_B1};

    int acc[2][8][4];
    #pragma unroll
    for (int mt = 0; mt < 2; ++mt)
        #pragma unroll
        for (int nt = 0; nt < 8; ++nt)
            #pragma unroll
            for (int e = 0; e < 4; ++e) acc[mt][nt][e] = 0;

    // rows are 256 bytes (256 s8); each kb stage loads a 128-row x 128B tile
    auto issue = [&](int kb, int s) {
        const char* Asrc = (const char*)((kb < 4) ? g_hi : g_lo);          // hh,hh,hl,hl,lh,lh
        const char* Bsrc = (const char*)((kb >= 2 && kb < 4) ? g_lo : g_hi);
        const int kq = (kb & 1) * 128;
        #pragma unroll
        for (int it = 0; it < 4; ++it) {
            int idx2 = tid + it * 256;
            int row = idx2 >> 3, c = idx2 & 7;
            uint32_t soff = row * 128 + ((c ^ (row & 7)) * 16);
            cp16(smem_base + aoff[s] + soff, Asrc + (size_t)(bm + row) * 256 + kq + c * 16);
            cp16(smem_base + boff[s] + soff, Bsrc + (size_t)(bn + row) * 256 + kq + c * 16);
        }
    };

    issue(0, 0);
    CP_COMMIT();

    for (int kb = 0; kb < NUM_KB; ++kb) {
        const int s = kb & 1;
        if (kb < NUM_KB - 1) { issue(kb + 1, s ^ 1); CP_COMMIT(); CP_WAIT(1); }
        else CP_WAIT(0);
        __syncthreads();

        const uint32_t ab = smem_base + aoff[s];
        const uint32_t bb = smem_base + boff[s];
        #pragma unroll
        for (int ks = 0; ks < 4; ++ks) {          // 4 x 32B k-chunks per kb
            const int cb = ks * 2;
            uint32_t a[2][4];
            #pragma unroll
            for (int mt = 0; mt < 2; ++mt) {
                int row = wm * 32 + mt * 16 + (lane & 15);
                int ch  = (cb + (lane >> 4)) ^ (row & 7);
                ldsm4(a[mt][0], a[mt][1], a[mt][2], a[mt][3], ab + row * 128 + ch * 16);
            }
            uint32_t bf[8][2];
            #pragma unroll
            for (int p = 0; p < 4; ++p) {
                int row = wn * 64 + p * 16 + (lane & 7) + ((lane >> 4) << 3);
                int ch  = (cb + ((lane >> 3) & 1)) ^ (row & 7);
                uint32_t r0, r1, r2, r3;
                ldsm4(r0, r1, r2, r3, bb + row * 128 + ch * 16);
                bf[2 * p][0] = r0; bf[2 * p][1] = r1;
                bf[2 * p + 1][0] = r2; bf[2 * p + 1][1] = r3;
            }
            #pragma unroll
            for (int mt = 0; mt < 2; ++mt)
                #pragma unroll
                for (int nt = 0; nt < 8; ++nt)
                    mma_s8(acc[mt][nt], a[mt], bf[nt]);
        }
        if (kb == 1) {   // end of hh pass: weight hh by 256, reuse same accumulators
            #pragma unroll
            for (int mt = 0; mt < 2; ++mt)
                #pragma unroll
                for (int nt = 0; nt < 8; ++nt)
                    #pragma unroll
                    for (int e = 0; e < 4; ++e) acc[mt][nt][e] <<= 8;
        }
        __syncthreads();
    }

    // ---- epilogue ----
    const int qr = lane >> 2, qc = lane & 3;
    float* Tt = reinterpret_cast<float*>(smem + SM_TILE);   // 128 x 129 floats

    float mx[2][2], mg[2][2], ml[2][2];
    #pragma unroll
    for (int mt = 0; mt < 2; ++mt)
        #pragma unroll
        for (int h = 0; h < 2; ++h) { mx[mt][h] = 0.0f; mg[mt][h] = BIG; ml[mt][h] = BIG; }

    #pragma unroll
    for (int mt = 0; mt < 2; ++mt) {
        #pragma unroll
        for (int h = 0; h < 2; ++h) {
            const int lr   = wm * 32 + mt * 16 + qr + 8 * h;
            const float rs = sqi[lr];
            const int   rt = tis[lr];
            float* drow = dist + (size_t)(bm + lr) * N + bn + wn * 64;
            #pragma unroll
            for (int nt = 0; nt < 8; ++nt) {
                const int c0  = nt * 8 + qc * 2;
                const int lc0 = wn * 64 + c0;
                float dot0 = (float)acc[mt][nt][2 * h + 0] * INV_DOT;
                float dot1 = (float)acc[mt][nt][2 * h + 1] * INV_DOT;
                float d0 = sqrtf(fmaxf(rs + sqj[lc0]     - 2.0f * dot0, 0.0f));
                float d1 = sqrtf(fmaxf(rs + sqj[lc0 + 1] - 2.0f * dot1, 0.0f));
                int t0 = tjs[lc0], t1 = tjs[lc0 + 1];
                if (t0 == rt)     mx[mt][h] = fmaxf(mx[mt][h], d0);
                else if (t0 > rt) mg[mt][h] = fminf(mg[mt][h], d0);
                else              ml[mt][h] = fminf(ml[mt][h], d0);
                if (t1 == rt)     mx[mt][h] = fmaxf(mx[mt][h], d1);
                else if (t1 > rt) mg[mt][h] = fminf(mg[mt][h], d1);
                else              ml[mt][h] = fminf(ml[mt][h], d1);
                if (diag) {
                    drow[c0]     = d0;
                    drow[c0 + 1] = d1;
                } else {
                    Tt[lr * 129 + lc0]     = d0;
                    Tt[lr * 129 + lc0 + 1] = d1;
                }
            }
        }
    }
    #pragma unroll
    for (int o = 1; o <= 2; o <<= 1) {
        #pragma unroll
        for (int mt = 0; mt < 2; ++mt)
            #pragma unroll
            for (int h = 0; h < 2; ++h) {
                mx[mt][h] = fmaxf(mx[mt][h], __shfl_xor_sync(0xffffffffu, mx[mt][h], o));
                mg[mt][h] = fminf(mg[mt][h], __shfl_xor_sync(0xffffffffu, mg[mt][h], o));
                ml[mt][h] = fminf(ml[mt][h], __shfl_xor_sync(0xffffffffu, ml[mt][h], o));
            }
    }
    if (qc == 0) {
        #pragma unroll
        for (int mt = 0; mt < 2; ++mt)
            #pragma unroll
            for (int h = 0; h < 2; ++h) {
                int gi = bm + wm * 32 + mt * 16 + qr + 8 * h;
                atomicMax(&g_max_eq[gi], __float_as_uint(mx[mt][h]));
                atomicMin(&g_min_gt[gi], __float_as_uint(mg[mt][h]));
                atomicMin(&g_min_lt[gi], __float_as_uint(ml[mt][h]));
            }
    }

    if (!diag) {
        __syncthreads();
        // orientation 1: rows of tile -> dist[bm+r][bn..]
        #pragma unroll
        for (int r0 = 0; r0 < 16; ++r0) {
            const int r = wid * 16 + r0;
            float* drow = dist + (size_t)(bm + r) * N + bn;
            #pragma unroll
            for (int ch = 0; ch < 4; ++ch)
                drow[ch * 32 + lane] = Tt[r * 129 + ch * 32 + lane];
        }
        // orientation 2 + j-row stats
        #pragma unroll
        for (int r0 = 0; r0 < 16; ++r0) {
            const int rp = wid * 16 + r0;
            const int tc = tjs[rp];
            float jm = 0.0f, jg = BIG, jl = BIG;
            float* drow = dist + (size_t)(bn + rp) * N + bm;
            #pragma unroll
            for (int ch = 0; ch < 4; ++ch) {
                const int i = ch * 32 + lane;
                float v = Tt[i * 129 + rp];
                drow[i] = v;
                int rt = tis[i];
                if (rt == tc)     jm = fmaxf(jm, v);
                else if (rt > tc) jg = fminf(jg, v);
                else              jl = fminf(jl, v);
            }
            #pragma unroll
            for (int o = 16; o >= 1; o >>= 1) {
                jm = fmaxf(jm, __shfl_xor_sync(0xffffffffu, jm, o));
                jg = fminf(jg, __shfl_xor_sync(0xffffffffu, jg, o));
                jl = fminf(jl, __shfl_xor_sync(0xffffffffu, jl, o));
            }
            if (lane == 0) {
                atomicMax(&g_max_eq[bn + rp], __float_as_uint(jm));
                atomicMin(&g_min_gt[bn + rp], __float_as_uint(jg));
                atomicMin(&g_min_lt[bn + rp], __float_as_uint(jl));
            }
        }
    }
}

__global__ void k_final(const int* __restrict__ T, float* __restrict__ out, int cnt_idx) {
    __shared__ float wsum[32];
    __shared__ int   wcnt[32];
    __shared__ int   hist[4];
    int tid = threadIdx.x, lane = tid & 31, warp = tid >> 5;
    if (tid < 4) hist[tid] = 0;
    __syncthreads();
    int r4 = tid * 4;
    int4  tt = *reinterpret_cast<const int4*>(&T[r4]);
    int tts[4] = {tt.x, tt.y, tt.z, tt.w};
    #pragma unroll
    for (int b = 0; b < 4; ++b) {
        int m = ((tts[0] == b) ? 1 : 0) + ((tts[1] == b) ? 1 : 0)
              + ((tts[2] == b) ? 1 : 0) + ((tts[3] == b) ? 1 : 0);
        #pragma unroll
        for (int o = 16; o >= 1; o >>= 1) m += __shfl_xor_sync(0xffffffffu, m, o);
        if (lane == 0) atomicAdd(&hist[b], m);
    }
    uint4 me = *reinterpret_cast<const uint4*>(&g_max_eq[r4]);
    uint4 gg = *reinterpret_cast<const uint4*>(&g_min_gt[r4]);
    uint4 ll = *reinterpret_cast<const uint4*>(&g_min_lt[r4]);
    __syncthreads();
    float s = 0.0f; int c = 0;
    {
        unsigned mes[4] = {me.x, me.y, me.z, me.w};
        unsigned ggs[4] = {gg.x, gg.y, gg.z, gg.w};
        unsigned lls[4] = {ll.x, ll.y, ll.z, ll.w};
        #pragma unroll
        for (int e = 0; e < 4; ++e) {
            float mxv = __uint_as_float(mes[e]);
            float mgv = __uint_as_float(ggs[e]);
            float mlv = __uint_as_float(lls[e]);
            s += fmaxf(mxv - fabsf(mgv - mlv) + MARGIN, 0.0f);
            c += (hist[tts[e] & 3] == 1) ? 1 : 0;
        }
    }
    #pragma unroll
    for (int o = 16; o >= 1; o >>= 1) {
        s += __shfl_xor_sync(0xffffffffu, s, o);
        c += __shfl_xor_sync(0xffffffffu, c, o);
    }
    if (lane == 0) { wsum[warp] = s; wcnt[warp] = c; }
    __syncthreads();
    if (warp == 0) {
        s = wsum[lane]; c = wcnt[lane];
        #pragma unroll
        for (int o = 16; o >= 1; o >>= 1) {
            s += __shfl_xor_sync(0xffffffffu, s, o);
            c += __shfl_xor_sync(0xffffffffu, c, o);
        }
        if (lane == 0) { out[0] = s / (float)N; out[cnt_idx] = (float)c; }
    }
}

extern "C" void kernel_launch(void* const* d_in, const int* in_sizes, int n_in,
                              void* d_out, int out_size) {
    const float* X = (const float*)d_in[0];
    const int*   T = (const int*)d_in[1];
    float* out = (float*)d_out;

    static bool attr_done = false;
    if (!attr_done) {
        cudaFuncSetAttribute(k_dist_mma, cudaFuncAttributeMaxDynamicSharedMemorySize, SMEM_TOTAL);
        attr_done = true;
    }

    k_prep<<<N / 8, 256>>>(X, T);
    k_dist_mma<<<NTRI, 256, SMEM_TOTAL>>>(T, out + 1);
    k_final<<<1, 1024>>>(T, out, out_size - 1);
}

// round 11
// speedup vs baseline: 2.5271x; 2.5271x over previous
#include <cuda_runtime.h>
#include <cuda_fp16.h>
#include <cstdint>

constexpr int N = 4096;
constexpr int K = 256;
constexpr float MARGIN = 0.3f;
constexpr float BIG = 10000.0f;

// ---------------- scratch (device globals; no runtime alloc) ----------------
__device__ __align__(16) float    g_sq[N];
__device__ __align__(16) unsigned g_max_eq[N];
__device__ __align__(16) unsigned g_min_gt[N];
__device__ __align__(16) unsigned g_min_lt[N];
__device__ __align__(16) __half   g_Xh[(size_t)N * K];   // fp16 copy of X

// ---------------- PTX helpers (base ISA only) ----------------
__device__ __forceinline__ uint32_t smem_u32(const void* p) {
    uint32_t a;
    asm("{ .reg .u64 t; cvta.to.shared.u64 t, %1; cvt.u32.u64 %0, t; }" : "=r"(a) : "l"(p));
    return a;
}
__device__ __forceinline__ void cp16(uint32_t saddr, const void* g) {
    asm volatile("cp.async.cg.shared.global [%0], [%1], 16;" :: "r"(saddr), "l"(g));
}
#define CP_COMMIT() asm volatile("cp.async.commit_group;" ::: "memory")
#define CP_WAIT(n)  asm volatile("cp.async.wait_group %0;" :: "n"(n) : "memory")

__device__ __forceinline__ void ldsm4(uint32_t& r0, uint32_t& r1, uint32_t& r2, uint32_t& r3,
                                      uint32_t addr) {
    asm volatile("ldmatrix.sync.aligned.m8n8.x4.shared.b16 {%0,%1,%2,%3}, [%4];"
                 : "=r"(r0), "=r"(r1), "=r"(r2), "=r"(r3) : "r"(addr));
}
__device__ __forceinline__ void mma_f16(float* d, const uint32_t* a, const uint32_t* b) {
    asm volatile("mma.sync.aligned.m16n8k16.row.col.f32.f16.f16.f32 "
                 "{%0,%1,%2,%3},{%4,%5,%6,%7},{%8,%9},{%0,%1,%2,%3};"
                 : "+f"(d[0]), "+f"(d[1]), "+f"(d[2]), "+f"(d[3])
                 : "r"(a[0]), "r"(a[1]), "r"(a[2]), "r"(a[3]), "r"(b[0]), "r"(b[1]));
}

// ---------------- kernels ----------------
__global__ void k_prep(const float* __restrict__ X, const int* __restrict__ T) {
    int warp = threadIdx.x >> 5, lane = threadIdx.x & 31;
    int row = blockIdx.x * 8 + warp;
    const float4* p = reinterpret_cast<const float4*>(X + (size_t)row * K);
    float4 a = p[lane * 2];
    float4 b = p[lane * 2 + 1];
    float xs[8] = {a.x, a.y, a.z, a.w, b.x, b.y, b.z, b.w};
    float s = 0.0f;
    __half hb[8];
    #pragma unroll
    for (int e = 0; e < 8; ++e) {
        s = fmaf(xs[e], xs[e], s);
        hb[e] = __float2half_rn(xs[e]);
    }
    size_t off = (size_t)row * K + lane * 8;
    *reinterpret_cast<uint4*>(&g_Xh[off]) = *reinterpret_cast<uint4*>(hb);
    #pragma unroll
    for (int o = 16; o >= 1; o >>= 1) s += __shfl_xor_sync(0xffffffffu, s, o);
    if (lane == 0) {
        g_sq[row]     = s;
        g_max_eq[row] = 0u;
        g_min_gt[row] = __float_as_uint(BIG);
        g_min_lt[row] = __float_as_uint(BIG);
    }
}

// SMEM layout (dynamic):
//   [0] sqj[128]  [512] tj[128]  [1024] sqi[128]  [1536] ti[128]
//   mainloop:  [2048] A0(16K) [18432] B0 [34816] A1 [51200] B1   (end 67584)
//   epilogue:  [2048] staging tile 128 x 129 floats (66048 B, end 68096)
constexpr int SM_SQJ = 0, SM_TJ = 512, SM_SQI = 1024, SM_TI = 1536;
constexpr int SM_A0 = 2048, SM_B0 = 18432, SM_A1 = 34816, SM_B1 = 51200;
constexpr int SM_TILE = 2048;
constexpr int SMEM_TOTAL = 68096;
constexpr int NUM_KB = 4;    // single fp16 pass: K=256 / BK=64
constexpr int NBLK = 32;
constexpr int NTRI = NBLK * (NBLK + 1) / 2;  // 528

__global__ void __launch_bounds__(256, 2)
k_dist_mma(const int* __restrict__ T, float* __restrict__ dist) {
    extern __shared__ char smem[];
    const uint32_t smem_base = smem_u32(smem);
    const int tid  = threadIdx.x;
    const int lane = tid & 31, wid = tid >> 5;
    const int wm = wid & 3, wn = wid >> 2;        // warp tile: 32 rows x 64 cols

    // triangular decode: by >= bx
    int idx = blockIdx.x;
    int by = (int)((sqrtf(8.0f * (float)idx + 1.0f) - 1.0f) * 0.5f);
    while ((by + 1) * (by + 2) / 2 <= idx) ++by;
    while (by * (by + 1) / 2 > idx) --by;
    const int bx = idx - by * (by + 1) / 2;
    const int bm = by * 128;
    const int bn = bx * 128;
    const bool diag = (by == bx);

    float* sqj = reinterpret_cast<float*>(smem + SM_SQJ);
    int*   tjs = reinterpret_cast<int*>(smem + SM_TJ);
    float* sqi = reinterpret_cast<float*>(smem + SM_SQI);
    int*   tis = reinterpret_cast<int*>(smem + SM_TI);
    if (tid < 128) { sqj[tid] = g_sq[bn + tid]; tjs[tid] = T[bn + tid]; }
    else { int t2 = tid - 128; sqi[t2] = g_sq[bm + t2]; tis[t2] = T[bm + t2]; }

    const int aoff[2] = {SM_A0, SM_A1};
    const int boff[2] = {SM_B0, SM_B1};

    float acc[2][8][4];
    #pragma unroll
    for (int mt = 0; mt < 2; ++mt)
        #pragma unroll
        for (int nt = 0; nt < 8; ++nt)
            #pragma unroll
            for (int e = 0; e < 4; ++e) acc[mt][nt][e] = 0.0f;

    // rows are 512 bytes (256 fp16); each kb stage loads a 128-row x 128B tile
    auto issue = [&](int kb, int s) {
        const char* src = (const char*)g_Xh;
        const int kq = (kb & 3) * 128;
        #pragma unroll
        for (int it = 0; it < 4; ++it) {
            int idx2 = tid + it * 256;
            int row = idx2 >> 3, c = idx2 & 7;
            uint32_t soff = row * 128 + ((c ^ (row & 7)) * 16);
            cp16(smem_base + aoff[s] + soff, src + (size_t)(bm + row) * 512 + kq + c * 16);
            cp16(smem_base + boff[s] + soff, src + (size_t)(bn + row) * 512 + kq + c * 16);
        }
    };

    issue(0, 0);
    CP_COMMIT();

    for (int kb = 0; kb < NUM_KB; ++kb) {
        const int s = kb & 1;
        if (kb < NUM_KB - 1) { issue(kb + 1, s ^ 1); CP_COMMIT(); CP_WAIT(1); }
        else CP_WAIT(0);
        __syncthreads();

        const uint32_t ab = smem_base + aoff[s];
        const uint32_t bb = smem_base + boff[s];
        #pragma unroll
        for (int ks = 0; ks < 4; ++ks) {          // 4 x k16 steps per kb
            const int cb = ks * 2;
            uint32_t a[2][4];
            #pragma unroll
            for (int mt = 0; mt < 2; ++mt) {
                int row = wm * 32 + mt * 16 + (lane & 15);
                int ch  = (cb + (lane >> 4)) ^ (row & 7);
                ldsm4(a[mt][0], a[mt][1], a[mt][2], a[mt][3], ab + row * 128 + ch * 16);
            }
            uint32_t bf[8][2];
            #pragma unroll
            for (int p = 0; p < 4; ++p) {
                int row = wn * 64 + p * 16 + (lane & 7) + ((lane >> 4) << 3);
                int ch  = (cb + ((lane >> 3) & 1)) ^ (row & 7);
                uint32_t r0, r1, r2, r3;
                ldsm4(r0, r1, r2, r3, bb + row * 128 + ch * 16);
                bf[2 * p][0] = r0; bf[2 * p][1] = r1;
                bf[2 * p + 1][0] = r2; bf[2 * p + 1][1] = r3;
            }
            #pragma unroll
            for (int mt = 0; mt < 2; ++mt)
                #pragma unroll
                for (int nt = 0; nt < 8; ++nt)
                    mma_f16(acc[mt][nt], a[mt], bf[nt]);
        }
        __syncthreads();
    }

    // ---- epilogue ----
    const int qr = lane >> 2, qc = lane & 3;
    float* Tt = reinterpret_cast<float*>(smem + SM_TILE);   // 128 x 129 floats

    float mx[2][2], mg[2][2], ml[2][2];
    #pragma unroll
    for (int mt = 0; mt < 2; ++mt)
        #pragma unroll
        for (int h = 0; h < 2; ++h) { mx[mt][h] = 0.0f; mg[mt][h] = BIG; ml[mt][h] = BIG; }

    #pragma unroll
    for (int mt = 0; mt < 2; ++mt) {
        #pragma unroll
        for (int h = 0; h < 2; ++h) {
            const int lr   = wm * 32 + mt * 16 + qr + 8 * h;
            const float rs = sqi[lr];
            const int   rt = tis[lr];
            float* drow = dist + (size_t)(bm + lr) * N + bn + wn * 64;
            #pragma unroll
            for (int nt = 0; nt < 8; ++nt) {
                const int c0  = nt * 8 + qc * 2;
                const int lc0 = wn * 64 + c0;
                float d0 = sqrtf(fmaxf(rs + sqj[lc0]     - 2.0f * acc[mt][nt][2 * h + 0], 0.0f));
                float d1 = sqrtf(fmaxf(rs + sqj[lc0 + 1] - 2.0f * acc[mt][nt][2 * h + 1], 0.0f));
                int t0 = tjs[lc0], t1 = tjs[lc0 + 1];
                if (t0 == rt)     mx[mt][h] = fmaxf(mx[mt][h], d0);
                else if (t0 > rt) mg[mt][h] = fminf(mg[mt][h], d0);
                else              ml[mt][h] = fminf(ml[mt][h], d0);
                if (t1 == rt)     mx[mt][h] = fmaxf(mx[mt][h], d1);
                else if (t1 > rt) mg[mt][h] = fminf(mg[mt][h], d1);
                else              ml[mt][h] = fminf(ml[mt][h], d1);
                if (diag) {
                    drow[c0]     = d0;
                    drow[c0 + 1] = d1;
                } else {
                    Tt[lr * 129 + lc0]     = d0;
                    Tt[lr * 129 + lc0 + 1] = d1;
                }
            }
        }
    }
    #pragma unroll
    for (int o = 1; o <= 2; o <<= 1) {
        #pragma unroll
        for (int mt = 0; mt < 2; ++mt)
            #pragma unroll
            for (int h = 0; h < 2; ++h) {
                mx[mt][h] = fmaxf(mx[mt][h], __shfl_xor_sync(0xffffffffu, mx[mt][h], o));
                mg[mt][h] = fminf(mg[mt][h], __shfl_xor_sync(0xffffffffu, mg[mt][h], o));
                ml[mt][h] = fminf(ml[mt][h], __shfl_xor_sync(0xffffffffu, ml[mt][h], o));
            }
    }
    if (qc == 0) {
        #pragma unroll
        for (int mt = 0; mt < 2; ++mt)
            #pragma unroll
            for (int h = 0; h < 2; ++h) {
                int gi = bm + wm * 32 + mt * 16 + qr + 8 * h;
                atomicMax(&g_max_eq[gi], __float_as_uint(mx[mt][h]));
                atomicMin(&g_min_gt[gi], __float_as_uint(mg[mt][h]));
                atomicMin(&g_min_lt[gi], __float_as_uint(ml[mt][h]));
            }
    }

    if (!diag) {
        __syncthreads();
        // orientation 1: rows of tile -> dist[bm+r][bn..]
        #pragma unroll
        for (int r0 = 0; r0 < 16; ++r0) {
            const int r = wid * 16 + r0;
            float* drow = dist + (size_t)(bm + r) * N + bn;
            #pragma unroll
            for (int ch = 0; ch < 4; ++ch)
                drow[ch * 32 + lane] = Tt[r * 129 + ch * 32 + lane];
        }
        // orientation 2 + j-row stats
        #pragma unroll
        for (int r0 = 0; r0 < 16; ++r0) {
            const int rp = wid * 16 + r0;
            const int tc = tjs[rp];
            float jm = 0.0f, jg = BIG, jl = BIG;
            float* drow = dist + (size_t)(bn + rp) * N + bm;
            #pragma unroll
            for (int ch = 0; ch < 4; ++ch) {
                const int i = ch * 32 + lane;
                float v = Tt[i * 129 + rp];
                drow[i] = v;
                int rt = tis[i];
                if (rt == tc)     jm = fmaxf(jm, v);
                else if (rt > tc) jg = fminf(jg, v);
                else              jl = fminf(jl, v);
            }
            #pragma unroll
            for (int o = 16; o >= 1; o >>= 1) {
                jm = fmaxf(jm, __shfl_xor_sync(0xffffffffu, jm, o));
                jg = fminf(jg, __shfl_xor_sync(0xffffffffu, jg, o));
                jl = fminf(jl, __shfl_xor_sync(0xffffffffu, jl, o));
            }
            if (lane == 0) {
                atomicMax(&g_max_eq[bn + rp], __float_as_uint(jm));
                atomicMin(&g_min_gt[bn + rp], __float_as_uint(jg));
                atomicMin(&g_min_lt[bn + rp], __float_as_uint(jl));
            }
        }
    }
}

__global__ void k_final(const int* __restrict__ T, float* __restrict__ out, int cnt_idx) {
    __shared__ float wsum[32];
    __shared__ int   wcnt[32];
    __shared__ int   hist[4];
    int tid = threadIdx.x, lane = tid & 31, warp = tid >> 5;
    if (tid < 4) hist[tid] = 0;
    __syncthreads();
    int r4 = tid * 4;
    int4  tt = *reinterpret_cast<const int4*>(&T[r4]);
    int tts[4] = {tt.x, tt.y, tt.z, tt.w};
    #pragma unroll
    for (int b = 0; b < 4; ++b) {
        int m = ((tts[0] == b) ? 1 : 0) + ((tts[1] == b) ? 1 : 0)
              + ((tts[2] == b) ? 1 : 0) + ((tts[3] == b) ? 1 : 0);
        #pragma unroll
        for (int o = 16; o >= 1; o >>= 1) m += __shfl_xor_sync(0xffffffffu, m, o);
        if (lane == 0) atomicAdd(&hist[b], m);
    }
    uint4 me = *reinterpret_cast<const uint4*>(&g_max_eq[r4]);
    uint4 gg = *reinterpret_cast<const uint4*>(&g_min_gt[r4]);
    uint4 ll = *reinterpret_cast<const uint4*>(&g_min_lt[r4]);
    __syncthreads();
    float s = 0.0f; int c = 0;
    {
        unsigned mes[4] = {me.x, me.y, me.z, me.w};
        unsigned ggs[4] = {gg.x, gg.y, gg.z, gg.w};
        unsigned lls[4] = {ll.x, ll.y, ll.z, ll.w};
        #pragma unroll
        for (int e = 0; e < 4; ++e) {
            float mxv = __uint_as_float(mes[e]);
            float mgv = __uint_as_float(ggs[e]);
            float mlv = __uint_as_float(lls[e]);
            s += fmaxf(mxv - fabsf(mgv - mlv) + MARGIN, 0.0f);
            c += (hist[tts[e] & 3] == 1) ? 1 : 0;
        }
    }
    #pragma unroll
    for (int o = 16; o >= 1; o >>= 1) {
        s += __shfl_xor_sync(0xffffffffu, s, o);
        c += __shfl_xor_sync(0xffffffffu, c, o);
    }
    if (lane == 0) { wsum[warp] = s; wcnt[warp] = c; }
    __syncthreads();
    if (warp == 0) {
        s = wsum[lane]; c = wcnt[lane];
        #pragma unroll
        for (int o = 16; o >= 1; o >>= 1) {
            s += __shfl_xor_sync(0xffffffffu, s, o);
            c += __shfl_xor_sync(0xffffffffu, c, o);
        }
        if (lane == 0) { out[0] = s / (float)N; out[cnt_idx] = (float)c; }
    }
}

extern "C" void kernel_launch(void* const* d_in, const int* in_sizes, int n_in,
                              void* d_out, int out_size) {
    const float* X = (const float*)d_in[0];
    const int*   T = (const int*)d_in[1];
    float* out = (float*)d_out;

    static bool attr_done = false;
    if (!attr_done) {
        cudaFuncSetAttribute(k_dist_mma, cudaFuncAttributeMaxDynamicSharedMemorySize, SMEM_TOTAL);
        attr_done = true;
    }

    k_prep<<<N / 8, 256>>>(X, T);
    k_dist_mma<<<NTRI, 256, SMEM_TOTAL>>>(T, out + 1);
    k_final<<<1, 1024>>>(T, out, out_size - 1);
}

// round 12
// speedup vs baseline: 2.5837x; 1.0224x over previous
#include <cuda_runtime.h>
#include <cuda_fp16.h>
#include <cstdint>

constexpr int N = 4096;
constexpr int K = 256;
constexpr float MARGIN = 0.3f;
constexpr float BIG = 10000.0f;

// ---------------- scratch (device globals; no runtime alloc) ----------------
__device__ __align__(16) float    g_sq[N];
__device__ __align__(16) unsigned g_max_eq[N];
__device__ __align__(16) unsigned g_min_gt[N];
__device__ __align__(16) unsigned g_min_lt[N];
__device__              int       g_label_cnt[4];     // reset by k_final each run
__device__ __align__(16) __half   g_Xh[(size_t)N * K];

// ---------------- PTX helpers (base ISA only) ----------------
__device__ __forceinline__ uint32_t smem_u32(const void* p) {
    uint32_t a;
    asm("{ .reg .u64 t; cvta.to.shared.u64 t, %1; cvt.u32.u64 %0, t; }" : "=r"(a) : "l"(p));
    return a;
}
__device__ __forceinline__ void cp16(uint32_t saddr, const void* g) {
    asm volatile("cp.async.cg.shared.global [%0], [%1], 16;" :: "r"(saddr), "l"(g));
}
#define CP_COMMIT() asm volatile("cp.async.commit_group;" ::: "memory")
#define CP_WAIT(n)  asm volatile("cp.async.wait_group %0;" :: "n"(n) : "memory")

__device__ __forceinline__ void ldsm4(uint32_t& r0, uint32_t& r1, uint32_t& r2, uint32_t& r3,
                                      uint32_t addr) {
    asm volatile("ldmatrix.sync.aligned.m8n8.x4.shared.b16 {%0,%1,%2,%3}, [%4];"
                 : "=r"(r0), "=r"(r1), "=r"(r2), "=r"(r3) : "r"(addr));
}
__device__ __forceinline__ void mma_f16(float* d, const uint32_t* a, const uint32_t* b) {
    asm volatile("mma.sync.aligned.m16n8k16.row.col.f32.f16.f16.f32 "
                 "{%0,%1,%2,%3},{%4,%5,%6,%7},{%8,%9},{%0,%1,%2,%3};"
                 : "+f"(d[0]), "+f"(d[1]), "+f"(d[2]), "+f"(d[3])
                 : "r"(a[0]), "r"(a[1]), "r"(a[2]), "r"(a[3]), "r"(b[0]), "r"(b[1]));
}

// ---------------- kernels ----------------
__global__ void k_prep(const float* __restrict__ X, const int* __restrict__ T) {
    int warp = threadIdx.x >> 5, lane = threadIdx.x & 31;
    int row = blockIdx.x * 8 + warp;
    const float4* p = reinterpret_cast<const float4*>(X + (size_t)row * K);
    float4 a = p[lane * 2];
    float4 b = p[lane * 2 + 1];
    float xs[8] = {a.x, a.y, a.z, a.w, b.x, b.y, b.z, b.w};
    float s = 0.0f;
    __half hb[8];
    #pragma unroll
    for (int e = 0; e < 8; ++e) {
        s = fmaf(xs[e], xs[e], s);
        hb[e] = __float2half_rn(xs[e]);
    }
    size_t off = (size_t)row * K + lane * 8;
    *reinterpret_cast<uint4*>(&g_Xh[off]) = *reinterpret_cast<uint4*>(hb);
    #pragma unroll
    for (int o = 16; o >= 1; o >>= 1) s += __shfl_xor_sync(0xffffffffu, s, o);
    if (lane == 0) {
        g_sq[row]     = s;
        g_max_eq[row] = 0u;
        g_min_gt[row] = __float_as_uint(BIG);
        g_min_lt[row] = __float_as_uint(BIG);
        atomicAdd(&g_label_cnt[T[row] & 3], 1);
    }
}

// SMEM layout (dynamic):
//   [0] sqj[128]  [512] tj[128]  [1024] sqi[128]  [1536] ti[128]
//   mainloop:  [2048] A0(16K) [18432] B0 [34816] A1 [51200] B1   (end 67584)
//   epilogue:  [2048] staging tile 128 x 129 floats, TRANSPOSED (col-major)
constexpr int SM_SQJ = 0, SM_TJ = 512, SM_SQI = 1024, SM_TI = 1536;
constexpr int SM_A0 = 2048, SM_B0 = 18432, SM_A1 = 34816, SM_B1 = 51200;
constexpr int SM_TILE = 2048;
constexpr int SMEM_TOTAL = 68096;
constexpr int NUM_KB = 4;    // single fp16 pass: K=256 / BK=64
constexpr int NBLK = 32;
constexpr int NOFF = NBLK * (NBLK - 1) / 2;  // 496 off-diagonal blocks
constexpr int NTRI = NOFF + NBLK;            // 528 total; diagonals last

__global__ void __launch_bounds__(256, 2)
k_dist_mma(const int* __restrict__ T, float* __restrict__ dist) {
    extern __shared__ char smem[];
    const uint32_t smem_base = smem_u32(smem);
    const int tid  = threadIdx.x;
    const int lane = tid & 31, wid = tid >> 5;
    const int wm = wid & 3, wn = wid >> 2;        // warp tile: 32 rows x 64 cols

    // block decode: off-diagonal blocks first (bids 0..495), diagonals last
    int by, bx;
    if (blockIdx.x < NOFF) {
        int idx = blockIdx.x;                      // strict lower triangle of 31 rows
        int r = (int)((sqrtf(8.0f * (float)idx + 1.0f) - 1.0f) * 0.5f);
        while ((r + 1) * (r + 2) / 2 <= idx) ++r;
        while (r * (r + 1) / 2 > idx) --r;
        bx = idx - r * (r + 1) / 2;
        by = r + 1;                                // by > bx
    } else {
        by = bx = blockIdx.x - NOFF;
    }
    const int bm = by * 128;
    const int bn = bx * 128;
    const bool diag = (by == bx);

    float* sqj = reinterpret_cast<float*>(smem + SM_SQJ);
    int*   tjs = reinterpret_cast<int*>(smem + SM_TJ);
    float* sqi = reinterpret_cast<float*>(smem + SM_SQI);
    int*   tis = reinterpret_cast<int*>(smem + SM_TI);
    if (tid < 128) { sqj[tid] = g_sq[bn + tid]; tjs[tid] = T[bn + tid]; }
    else { int t2 = tid - 128; sqi[t2] = g_sq[bm + t2]; tis[t2] = T[bm + t2]; }

    const int aoff[2] = {SM_A0, SM_A1};
    const int boff[2] = {SM_B0, SM_B1};

    float acc[2][8][4];
    #pragma unroll
    for (int mt = 0; mt < 2; ++mt)
        #pragma unroll
        for (int nt = 0; nt < 8; ++nt)
            #pragma unroll
            for (int e = 0; e < 4; ++e) acc[mt][nt][e] = 0.0f;

    auto issue = [&](int kb, int s) {
        const char* src = (const char*)g_Xh;
        const int kq = (kb & 3) * 128;
        #pragma unroll
        for (int it = 0; it < 4; ++it) {
            int idx2 = tid + it * 256;
            int row = idx2 >> 3, c = idx2 & 7;
            uint32_t soff = row * 128 + ((c ^ (row & 7)) * 16);
            cp16(smem_base + aoff[s] + soff, src + (size_t)(bm + row) * 512 + kq + c * 16);
            cp16(smem_base + boff[s] + soff, src + (size_t)(bn + row) * 512 + kq + c * 16);
        }
    };

    issue(0, 0);
    CP_COMMIT();

    for (int kb = 0; kb < NUM_KB; ++kb) {
        const int s = kb & 1;
        if (kb < NUM_KB - 1) { issue(kb + 1, s ^ 1); CP_COMMIT(); CP_WAIT(1); }
        else CP_WAIT(0);
        __syncthreads();

        const uint32_t ab = smem_base + aoff[s];
        const uint32_t bb = smem_base + boff[s];
        #pragma unroll
        for (int ks = 0; ks < 4; ++ks) {
            const int cb = ks * 2;
            uint32_t a[2][4];
            #pragma unroll
            for (int mt = 0; mt < 2; ++mt) {
                int row = wm * 32 + mt * 16 + (lane & 15);
                int ch  = (cb + (lane >> 4)) ^ (row & 7);
                ldsm4(a[mt][0], a[mt][1], a[mt][2], a[mt][3], ab + row * 128 + ch * 16);
            }
            uint32_t bf[8][2];
            #pragma unroll
            for (int p = 0; p < 4; ++p) {
                int row = wn * 64 + p * 16 + (lane & 7) + ((lane >> 4) << 3);
                int ch  = (cb + ((lane >> 3) & 1)) ^ (row & 7);
                uint32_t r0, r1, r2, r3;
                ldsm4(r0, r1, r2, r3, bb + row * 128 + ch * 16);
                bf[2 * p][0] = r0; bf[2 * p][1] = r1;
                bf[2 * p + 1][0] = r2; bf[2 * p + 1][1] = r3;
            }
            #pragma unroll
            for (int mt = 0; mt < 2; ++mt)
                #pragma unroll
                for (int nt = 0; nt < 8; ++nt)
                    mma_f16(acc[mt][nt], a[mt], bf[nt]);
        }
        __syncthreads();
    }

    // ---- epilogue ----
    // orientation-1 stores go straight from registers; staging tile is written
    // TRANSPOSED (Tt[col][row]) so the mirror pass reads/writes linearly.
    const int qr = lane >> 2, qc = lane & 3;
    float* Tt = reinterpret_cast<float*>(smem + SM_TILE);   // 128 cols x 129 pitch

    float mx[2][2], mg[2][2], ml[2][2];
    #pragma unroll
    for (int mt = 0; mt < 2; ++mt)
        #pragma unroll
        for (int h = 0; h < 2; ++h) { mx[mt][h] = 0.0f; mg[mt][h] = BIG; ml[mt][h] = BIG; }

    #pragma unroll
    for (int mt = 0; mt < 2; ++mt) {
        #pragma unroll
        for (int h = 0; h < 2; ++h) {
            const int lr   = wm * 32 + mt * 16 + qr + 8 * h;
            const float rs = sqi[lr];
            const int   rt = tis[lr];
            float* drow = dist + (size_t)(bm + lr) * N + bn;
            #pragma unroll
            for (int nt = 0; nt < 8; ++nt) {
                const int lc0 = wn * 64 + nt * 8 + qc * 2;
                float d0 = sqrtf(fmaxf(rs + sqj[lc0]     - 2.0f * acc[mt][nt][2 * h + 0], 0.0f));
                float d1 = sqrtf(fmaxf(rs + sqj[lc0 + 1] - 2.0f * acc[mt][nt][2 * h + 1], 0.0f));
                int t0 = tjs[lc0], t1 = tjs[lc0 + 1];
                if (t0 == rt)     mx[mt][h] = fmaxf(mx[mt][h], d0);
                else if (t0 > rt) mg[mt][h] = fminf(mg[mt][h], d0);
                else              ml[mt][h] = fminf(ml[mt][h], d0);
                if (t1 == rt)     mx[mt][h] = fmaxf(mx[mt][h], d1);
                else if (t1 > rt) mg[mt][h] = fminf(mg[mt][h], d1);
                else              ml[mt][h] = fminf(ml[mt][h], d1);
                drow[lc0]     = d0;                  // direct store (4B aligned)
                drow[lc0 + 1] = d1;
                if (!diag) {                         // transposed staging
                    Tt[lc0 * 129 + lr]       = d0;
                    Tt[(lc0 + 1) * 129 + lr] = d1;
                }
            }
        }
    }
    #pragma unroll
    for (int o = 1; o <= 2; o <<= 1) {
        #pragma unroll
        for (int mt = 0; mt < 2; ++mt)
            #pragma unroll
            for (int h = 0; h < 2; ++h) {
                mx[mt][h] = fmaxf(mx[mt][h], __shfl_xor_sync(0xffffffffu, mx[mt][h], o));
                mg[mt][h] = fminf(mg[mt][h], __shfl_xor_sync(0xffffffffu, mg[mt][h], o));
                ml[mt][h] = fminf(ml[mt][h], __shfl_xor_sync(0xffffffffu, ml[mt][h], o));
            }
    }
    if (qc == 0) {
        #pragma unroll
        for (int mt = 0; mt < 2; ++mt)
            #pragma unroll
            for (int h = 0; h < 2; ++h) {
                int gi = bm + wm * 32 + mt * 16 + qr + 8 * h;
                atomicMax(&g_max_eq[gi], __float_as_uint(mx[mt][h]));
                atomicMin(&g_min_gt[gi], __float_as_uint(mg[mt][h]));
                atomicMin(&g_min_lt[gi], __float_as_uint(ml[mt][h]));
            }
    }

    if (!diag) {
        __syncthreads();
        // mirror pass: Tt row rp = original column -> dist[bn+rp][bm..] + j-stats
        #pragma unroll
        for (int r0 = 0; r0 < 16; ++r0) {
            const int rp = wid * 16 + r0;
            const int tc = tjs[rp];
            float jm = 0.0f, jg = BIG, jl = BIG;
            float* drow = dist + (size_t)(bn + rp) * N + bm;
            #pragma unroll
            for (int ch = 0; ch < 4; ++ch) {
                const int i = ch * 32 + lane;
                float v = Tt[rp * 129 + i];          // linear, conflict-free
                drow[i] = v;
                int rt = tis[i];
                if (rt == tc)     jm = fmaxf(jm, v);
                else if (rt > tc) jg = fminf(jg, v);
                else              jl = fminf(jl, v);
            }
            #pragma unroll
            for (int o = 16; o >= 1; o >>= 1) {
                jm = fmaxf(jm, __shfl_xor_sync(0xffffffffu, jm, o));
                jg = fminf(jg, __shfl_xor_sync(0xffffffffu, jg, o));
                jl = fminf(jl, __shfl_xor_sync(0xffffffffu, jl, o));
            }
            if (lane == 0) {
                atomicMax(&g_max_eq[bn + rp], __float_as_uint(jm));
                atomicMin(&g_min_gt[bn + rp], __float_as_uint(jg));
                atomicMin(&g_min_lt[bn + rp], __float_as_uint(jl));
            }
        }
    }
}

__global__ void k_final(const int* __restrict__ T, float* __restrict__ out, int cnt_idx) {
    __shared__ float wsum[32];
    __shared__ int   wcnt[32];
    __shared__ int   hist[4];
    int tid = threadIdx.x, lane = tid & 31, warp = tid >> 5;
    if (tid < 4) hist[tid] = g_label_cnt[tid];
    __syncthreads();
    if (tid < 4) g_label_cnt[tid] = 0;     // reset for next graph replay
    int r4 = tid * 4;
    int4  tt = *reinterpret_cast<const int4*>(&T[r4]);
    uint4 me = *reinterpret_cast<const uint4*>(&g_max_eq[r4]);
    uint4 gg = *reinterpret_cast<const uint4*>(&g_min_gt[r4]);
    uint4 ll = *reinterpret_cast<const uint4*>(&g_min_lt[r4]);
    int tts[4] = {tt.x, tt.y, tt.z, tt.w};
    float s = 0.0f; int c = 0;
    {
        unsigned mes[4] = {me.x, me.y, me.z, me.w};
        unsigned ggs[4] = {gg.x, gg.y, gg.z, gg.w};
        unsigned lls[4] = {ll.x, ll.y, ll.z, ll.w};
        #pragma unroll
        for (int e = 0; e < 4; ++e) {
            float mxv = __uint_as_float(mes[e]);
            float mgv = __uint_as_float(ggs[e]);
            float mlv = __uint_as_float(lls[e]);
            s += fmaxf(mxv - fabsf(mgv - mlv) + MARGIN, 0.0f);
            c += (hist[tts[e] & 3] == 1) ? 1 : 0;
        }
    }
    #pragma unroll
    for (int o = 16; o >= 1; o >>= 1) {
        s += __shfl_xor_sync(0xffffffffu, s, o);
        c += __shfl_xor_sync(0xffffffffu, c, o);
    }
    if (lane == 0) { wsum[warp] = s; wcnt[warp] = c; }
    __syncthreads();
    if (warp == 0) {
        s = wsum[lane]; c = wcnt[lane];
        #pragma unroll
        for (int o = 16; o >= 1; o >>= 1) {
            s += __shfl_xor_sync(0xffffffffu, s, o);
            c += __shfl_xor_sync(0xffffffffu, c, o);
        }
        if (lane == 0) { out[0] = s / (float)N; out[cnt_idx] = (float)c; }
    }
}

extern "C" void kernel_launch(void* const* d_in, const int* in_sizes, int n_in,
                              void* d_out, int out_size) {
    const float* X = (const float*)d_in[0];
    const int*   T = (const int*)d_in[1];
    float* out = (float*)d_out;

    static bool attr_done = false;
    if (!attr_done) {
        cudaFuncSetAttribute(k_dist_mma, cudaFuncAttributeMaxDynamicSharedMemorySize, SMEM_TOTAL);
        attr_done = true;
    }

    k_prep<<<N / 8, 256>>>(X, T);
    k_dist_mma<<<NTRI, 256, SMEM_TOTAL>>>(T, out + 1);
    k_final<<<1, 1024>>>(T, out, out_size - 1);
}

// round 13
// speedup vs baseline: 2.6375x; 1.0208x over previous
#include <cuda_runtime.h>
#include <cuda_fp16.h>
#include <cstdint>

constexpr int N = 4096;
constexpr int K = 256;
constexpr float MARGIN = 0.3f;
constexpr float BIG = 10000.0f;

// ---------------- scratch (device globals; no runtime alloc) ----------------
__device__ __align__(16) float    g_sq[N];
__device__ __align__(16) unsigned g_max_eq[N];
__device__ __align__(16) unsigned g_min_gt[N];
__device__ __align__(16) unsigned g_min_lt[N];
__device__              int       g_label_cnt[4];     // reset by k_final each run
// K-chunk-major, pre-swizzled fp16: g_Xq[kb][row][128B chunk]
__device__ __align__(16) __half   g_Xq[4][(size_t)N * 64];

// ---------------- PTX helpers (base ISA, sm_90-era; no 'a' features) --------
__device__ __forceinline__ uint32_t smem_u32(const void* p) {
    uint32_t a;
    asm("{ .reg .u64 t; cvta.to.shared.u64 t, %1; cvt.u32.u64 %0, t; }" : "=r"(a) : "l"(p));
    return a;
}
#define MBARRIER_INIT(addr, cnt) \
    asm volatile("mbarrier.init.shared.b64 [%0], %1;" :: "r"(addr), "r"(cnt) : "memory")
#define MBARRIER_EXPECT_TX(addr, bytes) \
    asm volatile("mbarrier.arrive.expect_tx.shared.b64 _, [%0], %1;" \
                 :: "r"(addr), "r"(bytes) : "memory")
#define MBARRIER_WAIT_PARITY(addr, par) do {                                             \
    uint32_t _m = (addr), _p = (par), _d;                                                \
    asm volatile("{ .reg .pred p; mbarrier.try_wait.parity.shared.b64 "                  \
                 "p, [%1], %2; selp.b32 %0,1,0,p; }" : "=r"(_d) : "r"(_m), "r"(_p) : "memory"); \
    if (!_d) {                                                                           \
        asm volatile("{ .reg .pred P1; WL%=: mbarrier.try_wait.parity.shared.b64 "       \
                     "P1, [%0], %1; @P1 bra.uni WD%=; bra.uni WL%=; WD%=: }"             \
                     :: "r"(_m), "r"(_p) : "memory");                                    \
    } } while (0)
__device__ __forceinline__ void bulk_g2s(uint32_t sdst, const void* gsrc, uint32_t bytes,
                                         uint32_t mbar) {
    asm volatile("cp.async.bulk.shared::cta.global.mbarrier::complete_tx::bytes "
                 "[%0], [%1], %2, [%3];"
                 :: "r"(sdst), "l"(gsrc), "r"(bytes), "r"(mbar) : "memory");
}
__device__ __forceinline__ void ldsm4(uint32_t& r0, uint32_t& r1, uint32_t& r2, uint32_t& r3,
                                      uint32_t addr) {
    asm volatile("ldmatrix.sync.aligned.m8n8.x4.shared.b16 {%0,%1,%2,%3}, [%4];"
                 : "=r"(r0), "=r"(r1), "=r"(r2), "=r"(r3) : "r"(addr));
}
__device__ __forceinline__ void mma_f16(float* d, const uint32_t* a, const uint32_t* b) {
    asm volatile("mma.sync.aligned.m16n8k16.row.col.f32.f16.f16.f32 "
                 "{%0,%1,%2,%3},{%4,%5,%6,%7},{%8,%9},{%0,%1,%2,%3};"
                 : "+f"(d[0]), "+f"(d[1]), "+f"(d[2]), "+f"(d[3])
                 : "r"(a[0]), "r"(a[1]), "r"(a[2]), "r"(a[3]), "r"(b[0]), "r"(b[1]));
}

// ---------------- kernels ----------------
// one warp per row: norm, fp16 convert into K-chunk-major PRE-SWIZZLED layout
__global__ void k_prep(const float* __restrict__ X, const int* __restrict__ T) {
    int warp = threadIdx.x >> 5, lane = threadIdx.x & 31;
    int row = blockIdx.x * 8 + warp;
    const float4* p = reinterpret_cast<const float4*>(X + (size_t)row * K);
    float4 a = p[lane * 2];
    float4 b = p[lane * 2 + 1];
    float xs[8] = {a.x, a.y, a.z, a.w, b.x, b.y, b.z, b.w};
    float s = 0.0f;
    __half hb[8];
    #pragma unroll
    for (int e = 0; e < 8; ++e) {
        s = fmaf(xs[e], xs[e], s);
        hb[e] = __float2half_rn(xs[e]);
    }
    // lane covers elements [lane*8, lane*8+8) = kb chunk (lane>>3), 16B sub-chunk (lane&7)
    int kb = lane >> 3, c = lane & 7;
    char* dst = (char*)g_Xq + (size_t)kb * N * 128 + (size_t)row * 128 + ((c ^ (row & 7)) * 16);
    *reinterpret_cast<uint4*>(dst) = *reinterpret_cast<uint4*>(hb);
    #pragma unroll
    for (int o = 16; o >= 1; o >>= 1) s += __shfl_xor_sync(0xffffffffu, s, o);
    if (lane == 0) {
        g_sq[row]     = s;
        g_max_eq[row] = 0u;
        g_min_gt[row] = __float_as_uint(BIG);
        g_min_lt[row] = __float_as_uint(BIG);
        atomicAdd(&g_label_cnt[T[row] & 3], 1);
    }
}

// SMEM layout (dynamic):
//   [0] sqj[128] [512] tj[128] [1024] sqi[128] [1536] ti[128]
//   [2048] mbar[2] (16B)
//   [3072] stage0: A(16K)+B(16K)  [35840] stage1: A+B       (end 68608)
//   epilogue: [3072] staging tile 128 x 129 floats (66048 B, end 69120)
constexpr int SM_SQJ = 0, SM_TJ = 512, SM_SQI = 1024, SM_TI = 1536;
constexpr int SM_MBAR = 2048;
constexpr int SM_STAGE = 3072;
constexpr int STAGE_BYTES = 32768;              // A 16K + B 16K
constexpr int SM_TILE = 3072;
constexpr int SMEM_TOTAL = 69120;
constexpr int NUM_KB = 4;
constexpr int NBLK = 32;
constexpr int NOFF = NBLK * (NBLK - 1) / 2;     // 496 off-diagonal blocks first
constexpr int NTRI = NOFF + NBLK;               // 528; diagonals last

__global__ void __launch_bounds__(256, 2)
k_dist_mma(const int* __restrict__ T, float* __restrict__ dist) {
    extern __shared__ char smem[];
    const uint32_t smem_base = smem_u32(smem);
    const int tid  = threadIdx.x;
    const int lane = tid & 31, wid = tid >> 5;
    const int wm = wid & 3, wn = wid >> 2;        // warp tile: 32 rows x 64 cols

    // block decode: off-diagonal first, diagonals last
    int by, bx;
    if (blockIdx.x < NOFF) {
        int idx = blockIdx.x;
        int r = (int)((sqrtf(8.0f * (float)idx + 1.0f) - 1.0f) * 0.5f);
        while ((r + 1) * (r + 2) / 2 <= idx) ++r;
        while (r * (r + 1) / 2 > idx) --r;
        bx = idx - r * (r + 1) / 2;
        by = r + 1;
    } else {
        by = bx = blockIdx.x - NOFF;
    }
    const int bm = by * 128;
    const int bn = bx * 128;
    const bool diag = (by == bx);

    float* sqj = reinterpret_cast<float*>(smem + SM_SQJ);
    int*   tjs = reinterpret_cast<int*>(smem + SM_TJ);
    float* sqi = reinterpret_cast<float*>(smem + SM_SQI);
    int*   tis = reinterpret_cast<int*>(smem + SM_TI);
    if (tid < 128) { sqj[tid] = g_sq[bn + tid]; tjs[tid] = T[bn + tid]; }
    else { int t2 = tid - 128; sqi[t2] = g_sq[bm + t2]; tis[t2] = T[bm + t2]; }

    if (tid == 0) {
        MBARRIER_INIT(smem_base + SM_MBAR, 1);
        MBARRIER_INIT(smem_base + SM_MBAR + 8, 1);
    }
    __syncthreads();

    float acc[2][8][4];
    #pragma unroll
    for (int mt = 0; mt < 2; ++mt)
        #pragma unroll
        for (int nt = 0; nt < 8; ++nt)
            #pragma unroll
            for (int e = 0; e < 4; ++e) acc[mt][nt][e] = 0.0f;

    // one bulk copy per operand per stage (contiguous, pre-swizzled 16 KB)
    auto issue = [&](int kb, int s) {
        const uint32_t mbar = smem_base + SM_MBAR + s * 8;
        const uint32_t sbase = smem_base + SM_STAGE + s * STAGE_BYTES;
        const char* src = (const char*)g_Xq + (size_t)kb * N * 128;
        MBARRIER_EXPECT_TX(mbar, 32768u);
        bulk_g2s(sbase,         src + (size_t)bm * 128, 16384u, mbar);
        bulk_g2s(sbase + 16384, src + (size_t)bn * 128, 16384u, mbar);
    };

    if (tid == 0) { issue(0, 0); issue(1, 1); }

    for (int kb = 0; kb < NUM_KB; ++kb) {
        const int s = kb & 1;
        MBARRIER_WAIT_PARITY(smem_base + SM_MBAR + s * 8, (kb >> 1) & 1);

        const uint32_t ab = smem_base + SM_STAGE + s * STAGE_BYTES;
        const uint32_t bb = ab + 16384;
        #pragma unroll
        for (int ks = 0; ks < 4; ++ks) {
            const int cb = ks * 2;
            uint32_t a[2][4];
            #pragma unroll
            for (int mt = 0; mt < 2; ++mt) {
                int row = wm * 32 + mt * 16 + (lane & 15);
                int ch  = (cb + (lane >> 4)) ^ (row & 7);
                ldsm4(a[mt][0], a[mt][1], a[mt][2], a[mt][3], ab + row * 128 + ch * 16);
            }
            uint32_t bf[8][2];
            #pragma unroll
            for (int p = 0; p < 4; ++p) {
                int row = wn * 64 + p * 16 + (lane & 7) + ((lane >> 4) << 3);
                int ch  = (cb + ((lane >> 3) & 1)) ^ (row & 7);
                uint32_t r0, r1, r2, r3;
                ldsm4(r0, r1, r2, r3, bb + row * 128 + ch * 16);
                bf[2 * p][0] = r0; bf[2 * p][1] = r1;
                bf[2 * p + 1][0] = r2; bf[2 * p + 1][1] = r3;
            }
            #pragma unroll
            for (int mt = 0; mt < 2; ++mt)
                #pragma unroll
                for (int nt = 0; nt < 8; ++nt)
                    mma_f16(acc[mt][nt], a[mt], bf[nt]);
        }
        __syncthreads();                       // all consumers done with stage s
        if (tid == 0 && kb + 2 < NUM_KB) issue(kb + 2, s);
    }

    // ---- epilogue (unchanged from R12) ----
    const int qr = lane >> 2, qc = lane & 3;
    float* Tt = reinterpret_cast<float*>(smem + SM_TILE);   // transposed staging

    float mx[2][2], mg[2][2], ml[2][2];
    #pragma unroll
    for (int mt = 0; mt < 2; ++mt)
        #pragma unroll
        for (int h = 0; h < 2; ++h) { mx[mt][h] = 0.0f; mg[mt][h] = BIG; ml[mt][h] = BIG; }

    #pragma unroll
    for (int mt = 0; mt < 2; ++mt) {
        #pragma unroll
        for (int h = 0; h < 2; ++h) {
            const int lr   = wm * 32 + mt * 16 + qr + 8 * h;
            const float rs = sqi[lr];
            const int   rt = tis[lr];
            float* drow = dist + (size_t)(bm + lr) * N + bn;
            #pragma unroll
            for (int nt = 0; nt < 8; ++nt) {
                const int lc0 = wn * 64 + nt * 8 + qc * 2;
                float d0 = sqrtf(fmaxf(rs + sqj[lc0]     - 2.0f * acc[mt][nt][2 * h + 0], 0.0f));
                float d1 = sqrtf(fmaxf(rs + sqj[lc0 + 1] - 2.0f * acc[mt][nt][2 * h + 1], 0.0f));
                int t0 = tjs[lc0], t1 = tjs[lc0 + 1];
                if (t0 == rt)     mx[mt][h] = fmaxf(mx[mt][h], d0);
                else if (t0 > rt) mg[mt][h] = fminf(mg[mt][h], d0);
                else              ml[mt][h] = fminf(ml[mt][h], d0);
                if (t1 == rt)     mx[mt][h] = fmaxf(mx[mt][h], d1);
                else if (t1 > rt) mg[mt][h] = fminf(mg[mt][h], d1);
                else              ml[mt][h] = fminf(ml[mt][h], d1);
                drow[lc0]     = d0;
                drow[lc0 + 1] = d1;
                if (!diag) {
                    Tt[lc0 * 129 + lr]       = d0;
                    Tt[(lc0 + 1) * 129 + lr] = d1;
                }
            }
        }
    }
    #pragma unroll
    for (int o = 1; o <= 2; o <<= 1) {
        #pragma unroll
        for (int mt = 0; mt < 2; ++mt)
            #pragma unroll
            for (int h = 0; h < 2; ++h) {
                mx[mt][h] = fmaxf(mx[mt][h], __shfl_xor_sync(0xffffffffu, mx[mt][h], o));
                mg[mt][h] = fminf(mg[mt][h], __shfl_xor_sync(0xffffffffu, mg[mt][h], o));
                ml[mt][h] = fminf(ml[mt][h], __shfl_xor_sync(0xffffffffu, ml[mt][h], o));
            }
    }
    if (qc == 0) {
        #pragma unroll
        for (int mt = 0; mt < 2; ++mt)
            #pragma unroll
            for (int h = 0; h < 2; ++h) {
                int gi = bm + wm * 32 + mt * 16 + qr + 8 * h;
                atomicMax(&g_max_eq[gi], __float_as_uint(mx[mt][h]));
                atomicMin(&g_min_gt[gi], __float_as_uint(mg[mt][h]));
                atomicMin(&g_min_lt[gi], __float_as_uint(ml[mt][h]));
            }
    }

    if (!diag) {
        __syncthreads();
        #pragma unroll
        for (int r0 = 0; r0 < 16; ++r0) {
            const int rp = wid * 16 + r0;
            const int tc = tjs[rp];
            float jm = 0.0f, jg = BIG, jl = BIG;
            float* drow = dist + (size_t)(bn + rp) * N + bm;
            #pragma unroll
            for (int ch = 0; ch < 4; ++ch) {
                const int i = ch * 32 + lane;
                float v = Tt[rp * 129 + i];
                drow[i] = v;
                int rt = tis[i];
                if (rt == tc)     jm = fmaxf(jm, v);
                else if (rt > tc) jg = fminf(jg, v);
                else              jl = fminf(jl, v);
            }
            #pragma unroll
            for (int o = 16; o >= 1; o >>= 1) {
                jm = fmaxf(jm, __shfl_xor_sync(0xffffffffu, jm, o));
                jg = fminf(jg, __shfl_xor_sync(0xffffffffu, jg, o));
                jl = fminf(jl, __shfl_xor_sync(0xffffffffu, jl, o));
            }
            if (lane == 0) {
                atomicMax(&g_max_eq[bn + rp], __float_as_uint(jm));
                atomicMin(&g_min_gt[bn + rp], __float_as_uint(jg));
                atomicMin(&g_min_lt[bn + rp], __float_as_uint(jl));
            }
        }
    }
}

__global__ void k_final(const int* __restrict__ T, float* __restrict__ out, int cnt_idx) {
    __shared__ float wsum[32];
    __shared__ int   wcnt[32];
    __shared__ int   hist[4];
    int tid = threadIdx.x, lane = tid & 31, warp = tid >> 5;
    if (tid < 4) hist[tid] = g_label_cnt[tid];
    __syncthreads();
    if (tid < 4) g_label_cnt[tid] = 0;     // reset for next graph replay
    int r4 = tid * 4;
    int4  tt = *reinterpret_cast<const int4*>(&T[r4]);
    uint4 me = *reinterpret_cast<const uint4*>(&g_max_eq[r4]);
    uint4 gg = *reinterpret_cast<const uint4*>(&g_min_gt[r4]);
    uint4 ll = *reinterpret_cast<const uint4*>(&g_min_lt[r4]);
    int tts[4] = {tt.x, tt.y, tt.z, tt.w};
    float s = 0.0f; int c = 0;
    {
        unsigned mes[4] = {me.x, me.y, me.z, me.w};
        unsigned ggs[4] = {gg.x, gg.y, gg.z, gg.w};
        unsigned lls[4] = {ll.x, ll.y, ll.z, ll.w};
        #pragma unroll
        for (int e = 0; e < 4; ++e) {
            float mxv = __uint_as_float(mes[e]);
            float mgv = __uint_as_float(ggs[e]);
            float mlv = __uint_as_float(lls[e]);
            s += fmaxf(mxv - fabsf(mgv - mlv) + MARGIN, 0.0f);
            c += (hist[tts[e] & 3] == 1) ? 1 : 0;
        }
    }
    #pragma unroll
    for (int o = 16; o >= 1; o >>= 1) {
        s += __shfl_xor_sync(0xffffffffu, s, o);
        c += __shfl_xor_sync(0xffffffffu, c, o);
    }
    if (lane == 0) { wsum[warp] = s; wcnt[warp] = c; }
    __syncthreads();
    if (warp == 0) {
        s = wsum[lane]; c = wcnt[lane];
        #pragma unroll
        for (int o = 16; o >= 1; o >>= 1) {
            s += __shfl_xor_sync(0xffffffffu, s, o);
            c += __shfl_xor_sync(0xffffffffu, c, o);
        }
        if (lane == 0) { out[0] = s / (float)N; out[cnt_idx] = (float)c; }
    }
}

extern "C" void kernel_launch(void* const* d_in, const int* in_sizes, int n_in,
                              void* d_out, int out_size) {
    const float* X = (const float*)d_in[0];
    const int*   T = (const int*)d_in[1];
    float* out = (float*)d_out;

    static bool attr_done = false;
    if (!attr_done) {
        cudaFuncSetAttribute(k_dist_mma, cudaFuncAttributeMaxDynamicSharedMemorySize, SMEM_TOTAL);
        attr_done = true;
    }

    k_prep<<<N / 8, 256>>>(X, T);
    k_dist_mma<<<NTRI, 256, SMEM_TOTAL>>>(T, out + 1);
    k_final<<<1, 1024>>>(T, out, out_size - 1);
}